// round 7
// baseline (speedup 1.0000x reference)
#include <cuda_runtime.h>
#include <cuda_bf16.h>
#include <cuda_fp16.h>
#include <math.h>
#include <stdint.h>

#define BB 2
#define SS 2048
#define HH 12
#define DD 64
#define BH (BB*HH)

#define TI 128
#define TJ 64
#define NTH 512

#define NELEM (BB*HH*SS*DD)
__device__ __nv_bfloat16 g_qh[NELEM], g_ql[NELEM];   // [bh][s][d]
__device__ __nv_bfloat16 g_kh[NELEM], g_kl[NELEM];   // [bh][s][d]
__device__ __half        g_vt[NELEM];                // [bh][d][s]
__device__ float         g_vsum[BH * DD];

// smem layout: padded rows of 72 elems (144 B)
#define ROWB 144
#define OQH 0                      // 128 x ROWB = 18432
#define OQL 18432
#define OBUF 36864                 // two 27648-byte K/V buffers
#define BKH 0
#define BKL 9216
#define BV  18432
#define BUF_BYTES 27648
#define SMEM_DYN (OBUF + 2 * BUF_BYTES)   // 92160
#define ACC_STRIDE 66

// ---------------------------------------------------------------------------
__device__ __forceinline__ void mma_bf16(float (&c)[4], const uint32_t* a,
                                         uint32_t b0, uint32_t b1) {
    asm volatile(
        "mma.sync.aligned.m16n8k16.row.col.f32.bf16.bf16.f32 "
        "{%0,%1,%2,%3}, {%4,%5,%6,%7}, {%8,%9}, {%0,%1,%2,%3};\n"
        : "+f"(c[0]), "+f"(c[1]), "+f"(c[2]), "+f"(c[3])
        : "r"(a[0]), "r"(a[1]), "r"(a[2]), "r"(a[3]), "r"(b0), "r"(b1));
}
__device__ __forceinline__ void mma_fp16(float (&c)[4], const uint32_t* a,
                                         uint32_t b0, uint32_t b1) {
    asm volatile(
        "mma.sync.aligned.m16n8k16.row.col.f32.f16.f16.f32 "
        "{%0,%1,%2,%3}, {%4,%5,%6,%7}, {%8,%9}, {%0,%1,%2,%3};\n"
        : "+f"(c[0]), "+f"(c[1]), "+f"(c[2]), "+f"(c[3])
        : "r"(a[0]), "r"(a[1]), "r"(a[2]), "r"(a[3]), "r"(b0), "r"(b1));
}

#define LDSM4(r0, r1, r2, r3, addr) \
    asm volatile("ldmatrix.sync.aligned.m8n8.x4.shared.b16 {%0,%1,%2,%3}, [%4];" \
        : "=r"(r0), "=r"(r1), "=r"(r2), "=r"(r3) : "r"(addr))

#define CP16(dst, src) \
    asm volatile("cp.async.cg.shared.global [%0], [%1], 16;" \
        :: "r"(dst), "l"(src) : "memory")
#define CP_COMMIT() asm volatile("cp.async.commit_group;" ::: "memory")
#define CP_WAIT(n)  asm volatile("cp.async.wait_group %0;" :: "n"(n) : "memory")

__device__ __forceinline__ uint32_t smem_u32(const void* p) {
    uint32_t a;
    asm("{ .reg .u64 t; cvta.to.shared.u64 t, %1; cvt.u32.u64 %0, t; }" : "=r"(a) : "l"(p));
    return a;
}
__device__ __forceinline__ uint32_t pack_half2(float lo, float hi) {
    __half2 t = __floats2half2_rn(lo, hi);
    return *(uint32_t*)&t;
}

// ---------------------------------------------------------------------------
__global__ void rotary_qk_kernel(const float* __restrict__ qkv,
                                 const float* __restrict__ cosb,
                                 const float* __restrict__ sinb) {
    int idx = blockIdx.x * blockDim.x + threadIdx.x;
    const int total = BB * SS * 2 * HH * 32;
    if (idx >= total) return;
    int d2 = idx & 31; int rest = idx >> 5;
    int h = rest % HH; rest /= HH;
    int t = rest & 1;  rest >>= 1;
    int s = rest % SS; int b = rest / SS;

    size_t qoff = ((((size_t)b * SS + s) * 3 + t) * HH + h) * DD + d2;
    float x1 = qkv[qoff];
    float x2 = qkv[qoff + 32];
    int coff = (s * 3 + t) * DD + d2;
    float c = cosb[coff], sn = sinb[coff];
    float o1 = x1 * c - x2 * sn;
    float o2 = x2 * c + x1 * sn;

    __nv_bfloat16 h1 = __float2bfloat16_rn(o1);
    __nv_bfloat16 l1 = __float2bfloat16_rn(o1 - __bfloat162float(h1));
    __nv_bfloat16 h2 = __float2bfloat16_rn(o2);
    __nv_bfloat16 l2 = __float2bfloat16_rn(o2 - __bfloat162float(h2));

    __nv_bfloat16* dh = (t == 0) ? g_qh : g_kh;
    __nv_bfloat16* dl = (t == 0) ? g_ql : g_kl;
    size_t doff = (((size_t)b * HH + h) * SS + s) * DD + d2;
    dh[doff] = h1; dh[doff + 32] = h2;
    dl[doff] = l1; dl[doff + 32] = l2;
}

// ---------------------------------------------------------------------------
__global__ void vtrans_kernel(const float* __restrict__ qkv) {
    __shared__ __half sT[64 * 72];
    const int bh = blockIdx.y;
    const int b = bh / HH, h = bh % HH;
    const int s0 = blockIdx.x * 64;
    const int tid = threadIdx.x;
    const int sl = tid >> 2;
    const int d2b = (tid & 3) * 8;
    const int s = s0 + sl;

    const float* base = qkv + (((size_t)(b * SS + s) * 3 + 2) * HH + h) * DD;
    #pragma unroll
    for (int i = 0; i < 8; i++) {
        int d = d2b + i;
        sT[d * 72 + sl]        = __float2half_rn(base[d]);
        sT[(d + 32) * 72 + sl] = __float2half_rn(base[d + 32]);
    }
    __syncthreads();
    #pragma unroll
    for (int c = tid; c < 512; c += 256) {
        int r = c >> 3, co = (c & 7) * 8;
        size_t dst = ((size_t)bh * DD + r) * SS + s0 + co;
        *(uint4*)(g_vt + dst) = *(const uint4*)(sT + r * 72 + co);
    }
}

// ---------------------------------------------------------------------------
__global__ void vsum_kernel() {
    const int bh = blockIdx.x;
    const int tid = threadIdx.x;
    const int d = tid >> 2;
    const int q = tid & 3;
    const __half* src = g_vt + ((size_t)bh * DD + d) * SS + q * 512;
    float s = 0.f;
    #pragma unroll 8
    for (int i = 0; i < 64; i++) {
        uint4 v = *(const uint4*)(src + i * 8);
        const __half2* h2 = (const __half2*)&v;
        #pragma unroll
        for (int k = 0; k < 4; k++) {
            float2 f = __half22float2(h2[k]);
            s += f.x + f.y;
        }
    }
    s += __shfl_xor_sync(0xffffffffu, s, 1);
    s += __shfl_xor_sync(0xffffffffu, s, 2);
    if (q == 0) g_vsum[bh * DD + d] = s;
}

// ---------------------------------------------------------------------------
// flash attention, 512 threads: warp (rg, jh) does 16 rows x 32 j-cols
// ---------------------------------------------------------------------------
__global__ void __launch_bounds__(NTH, 1)
attn_kernel(const int* __restrict__ seqlens,
            float* __restrict__ out_x,
            float* __restrict__ out_logits) {
    extern __shared__ char smem[];
    const uint32_t sb = smem_u32(smem);
    __shared__ float sMax[2][128];

    const int tid = threadIdx.x;
    const int wid = tid >> 5;
    const int lane = tid & 31;
    const int lq = lane >> 2;
    const int lr = lane & 3;
    const int rg = wid & 7;          // row group: rows rg*16 .. +16
    const int jh = wid >> 3;         // j-half: cols jh*32 .. +32

    const int bh = blockIdx.y;
    const int b = bh / HH;
    const int i0 = blockIdx.x * TI;
    const int seqlen = seqlens[b];
    const float inv2048 = 1.0f / 2048.0f;

    // ---------- fully-masked i-tile ----------
    if (i0 >= seqlen) {
        float4 fill = make_float4(-1e10f, -1e10f, -1e10f, -1e10f);
        float4* lg = (float4*)(out_logits + ((size_t)bh * SS + i0) * SS);
        #pragma unroll 4
        for (int c = tid; c < TI * SS / 4; c += NTH)
            lg[c] = fill;
        const float* vs = g_vsum + bh * DD;
        float4* xo = (float4*)(out_x + ((size_t)bh * SS + i0) * DD);
        for (int c = tid; c < TI * DD / 4; c += NTH) {
            int dcol = (c & 15) * 4;
            xo[c] = make_float4(vs[dcol] * inv2048, vs[dcol + 1] * inv2048,
                                vs[dcol + 2] * inv2048, vs[dcol + 3] * inv2048);
        }
        return;
    }

    const int jtmax = (seqlen + TJ - 1) / TJ;
    const size_t bh_off = (size_t)bh * SS * DD;
    const size_t v_off = (size_t)bh * DD * SS;

    const uint32_t lmo = (uint32_t)(lane & 7) * ROWB + (uint32_t)((lane >> 3) & 3) * 16;

    // ---- stage Q (hi/lo) into smem ----
    {
        const __nv_bfloat16* qh = g_qh + bh_off + (size_t)i0 * DD;
        const __nv_bfloat16* ql = g_ql + bh_off + (size_t)i0 * DD;
        #pragma unroll
        for (int c = tid; c < 1024; c += NTH) {
            int r = c >> 3, co = (c & 7) * 8;
            *(uint4*)(smem + OQH + r * ROWB + co * 2) = *(const uint4*)(qh + r * DD + co);
            *(uint4*)(smem + OQL + r * ROWB + co * 2) = *(const uint4*)(ql + r * DD + co);
        }
    }

    // ---- prefetch (1 chunk per array per thread) ----
    #define ISSUE_PREFETCH(JT, BUF) do { \
        uint32_t bba = sb + OBUF + (BUF) * BUF_BYTES; \
        const __nv_bfloat16* _kh = g_kh + bh_off + (size_t)(JT) * TJ * DD; \
        const __nv_bfloat16* _kl = g_kl + bh_off + (size_t)(JT) * TJ * DD; \
        const __half* _v = g_vt + v_off + (size_t)(JT) * TJ; \
        int c = tid; \
        int r = c >> 3, co = (c & 7) * 8; \
        uint32_t dof = (uint32_t)r * ROWB + co * 2; \
        CP16(bba + BKH + dof, _kh + r * DD + co); \
        CP16(bba + BKL + dof, _kl + r * DD + co); \
        CP16(bba + BV + dof, _v + (size_t)r * SS + co); \
        CP_COMMIT(); \
    } while (0)

    ISSUE_PREFETCH(0, 0);
    __syncthreads();   // Q smem visible for ldmatrix

    // ---- loop-invariant Q a-frags via ldmatrix ----
    uint32_t aQh[16], aQl[16];
    {
        const uint32_t qlmo = ((uint32_t)(lane & 7) + ((uint32_t)(lane >> 3) & 1) * 8) * ROWB
                            + ((uint32_t)(lane >> 4)) * 16;
        uint32_t qb0 = sb + OQH + (uint32_t)rg * 16 * ROWB + qlmo;
        uint32_t qb1 = sb + OQL + (uint32_t)rg * 16 * ROWB + qlmo;
        #pragma unroll
        for (int kt = 0; kt < 4; kt++) {
            LDSM4(aQh[kt*4+0], aQh[kt*4+1], aQh[kt*4+2], aQh[kt*4+3], qb0 + kt * 32);
            LDSM4(aQl[kt*4+0], aQl[kt*4+1], aQl[kt*4+2], aQl[kt*4+3], qb1 + kt * 32);
        }
    }

    const int rowA = i0 + rg * 16 + lq;
    const int rowB = rowA + 8;
    const bool rvA = rowA < seqlen;
    const bool rvB = rowB < seqlen;
    const int lrA = rg * 16 + lq;       // local row indices
    const int lrB = lrA + 8;

    float mA = -INFINITY, mB = -INFINITY, lA = 0.f, lB = 0.f;
    float acc[8][4];
    #pragma unroll
    for (int n = 0; n < 8; n++)
        #pragma unroll
        for (int q = 0; q < 4; q++) acc[n][q] = 0.f;

    float* lgA = out_logits + ((size_t)bh * SS + rowA) * SS;
    float* lgB = out_logits + ((size_t)bh * SS + rowB) * SS;

    for (int jt = 0; jt < jtmax; jt++) {
        if (jt + 1 < jtmax) {
            ISSUE_PREFETCH(jt + 1, (jt + 1) & 1);
            CP_WAIT(1);
        } else {
            CP_WAIT(0);
        }
        __syncthreads();

        const uint32_t bba = sb + OBUF + (jt & 1) * BUF_BYTES;
        const uint32_t uKh = bba + BKH, uKl = bba + BKL, uVh = bba + BV;

        // ---- S = Q K^T over this warp's 32 j-cols (3-product bf16) ----
        float s[4][4];
        #pragma unroll
        for (int nt = 0; nt < 4; nt++) {
            #pragma unroll
            for (int q = 0; q < 4; q++) s[nt][q] = 0.f;
            uint32_t kb[8], lb[8];
            uint32_t a0 = uKh + ((uint32_t)jh * 32 + nt * 8) * ROWB + lmo;
            uint32_t a1 = uKl + ((uint32_t)jh * 32 + nt * 8) * ROWB + lmo;
            LDSM4(kb[0], kb[1], kb[2], kb[3], a0);
            LDSM4(kb[4], kb[5], kb[6], kb[7], a0 + 64);
            LDSM4(lb[0], lb[1], lb[2], lb[3], a1);
            LDSM4(lb[4], lb[5], lb[6], lb[7], a1 + 64);
            #pragma unroll
            for (int kt = 0; kt < 4; kt++) {
                mma_bf16(s[nt], aQh + kt * 4, kb[2*kt], kb[2*kt+1]);
                mma_bf16(s[nt], aQl + kt * 4, kb[2*kt], kb[2*kt+1]);
                mma_bf16(s[nt], aQh + kt * 4, lb[2*kt], lb[2*kt+1]);
            }
        }

        // ---- scale + mask + stream logits ----
        const int jb = jt * TJ + jh * 32;
        #pragma unroll
        for (int nt = 0; nt < 4; nt++) {
            int col = jb + nt * 8 + 2 * lr;
            bool c0v = col < seqlen;
            bool c1v = (col + 1) < seqlen;
            float v0 = (rvA && c0v) ? s[nt][0] * 0.125f : -1e10f;
            float v1 = (rvA && c1v) ? s[nt][1] * 0.125f : -1e10f;
            float v2 = (rvB && c0v) ? s[nt][2] * 0.125f : -1e10f;
            float v3 = (rvB && c1v) ? s[nt][3] * 0.125f : -1e10f;
            *(float2*)(lgA + col) = make_float2(v0, v1);
            *(float2*)(lgB + col) = make_float2(v2, v3);
            s[nt][0] = v0; s[nt][1] = v1; s[nt][2] = v2; s[nt][3] = v3;
        }

        // ---- row max: quad reduce + cross-half exchange ----
        float tmA = -INFINITY, tmB = -INFINITY;
        #pragma unroll
        for (int nt = 0; nt < 4; nt++) {
            tmA = fmaxf(tmA, fmaxf(s[nt][0], s[nt][1]));
            tmB = fmaxf(tmB, fmaxf(s[nt][2], s[nt][3]));
        }
        tmA = fmaxf(tmA, __shfl_xor_sync(0xffffffffu, tmA, 1));
        tmA = fmaxf(tmA, __shfl_xor_sync(0xffffffffu, tmA, 2));
        tmB = fmaxf(tmB, __shfl_xor_sync(0xffffffffu, tmB, 1));
        tmB = fmaxf(tmB, __shfl_xor_sync(0xffffffffu, tmB, 2));
        if (lr == 0) {
            sMax[jh][lrA] = tmA;
            sMax[jh][lrB] = tmB;
        }
        __syncthreads();
        tmA = fmaxf(tmA, sMax[1 - jh][lrA]);
        tmB = fmaxf(tmB, sMax[1 - jh][lrB]);

        float mnA = fmaxf(mA, tmA), mnB = fmaxf(mB, tmB);
        float fA = __expf(mA - mnA), fB = __expf(mB - mnB);
        mA = mnA; mB = mnB;

        float sumA = 0.f, sumB = 0.f;
        #pragma unroll
        for (int nt = 0; nt < 4; nt++) {
            s[nt][0] = __expf(s[nt][0] - mnA);
            s[nt][1] = __expf(s[nt][1] - mnA);
            s[nt][2] = __expf(s[nt][2] - mnB);
            s[nt][3] = __expf(s[nt][3] - mnB);
            sumA += s[nt][0] + s[nt][1];
            sumB += s[nt][2] + s[nt][3];
        }
        sumA += __shfl_xor_sync(0xffffffffu, sumA, 1);
        sumA += __shfl_xor_sync(0xffffffffu, sumA, 2);
        sumB += __shfl_xor_sync(0xffffffffu, sumB, 1);
        sumB += __shfl_xor_sync(0xffffffffu, sumB, 2);
        lA = lA * fA + sumA;     // own half only; combined at end
        lB = lB * fB + sumB;

        #pragma unroll
        for (int nt = 0; nt < 8; nt++) {
            acc[nt][0] *= fA; acc[nt][1] *= fA;
            acc[nt][2] *= fB; acc[nt][3] *= fB;
        }

        // ---- pack P (own 32 j) into fp16 a-frags ----
        uint32_t aP[8];
        #pragma unroll
        for (int kt = 0; kt < 2; kt++) {
            #pragma unroll
            for (int g = 0; g < 4; g++) {
                int nt = 2 * kt + (g >> 1);
                float p0 = s[nt][(g & 1) ? 2 : 0];
                float p1 = s[nt][(g & 1) ? 3 : 1];
                aP[kt * 4 + g] = pack_half2(p0, p1);
            }
        }

        // ---- X += P V : own j-half, full d (8 d-chunks) ----
        #pragma unroll
        for (int nt = 0; nt < 8; nt++) {
            uint32_t vb[4];
            uint32_t a0 = uVh + (uint32_t)nt * (8 * ROWB) + (uint32_t)jh * 64 + lmo;
            LDSM4(vb[0], vb[1], vb[2], vb[3], a0);
            mma_fp16(acc[nt], aP, vb[0], vb[1]);
            mma_fp16(acc[nt], aP + 4, vb[2], vb[3]);
        }
        __syncthreads();
    }

    // ---- tail fill: logits cols [jtmax*TJ, SS) ----
    {
        const int ctail = SS - jtmax * TJ;
        if (ctail > 0) {
            float4 fill = make_float4(-1e10f, -1e10f, -1e10f, -1e10f);
            float* base = out_logits + ((size_t)bh * SS + i0) * SS + jtmax * TJ;
            const int c4 = ctail / 4;
            for (int c = tid; c < TI * c4; c += NTH) {
                int r = c / c4, cc = (c % c4) * 4;
                *(float4*)(base + (size_t)r * SS + cc) = fill;
            }
        }
    }

    // ---- cross-half combine: l and acc ----
    float* sAcc = (float*)(smem + OBUF);    // 128 x ACC_STRIDE floats (33.8 KB)
    if (lr == 0) {
        sMax[jh][lrA] = lA;
        sMax[jh][lrB] = lB;
    }
    if (jh == 1) {
        #pragma unroll
        for (int nt = 0; nt < 8; nt++) {
            int col = nt * 8 + 2 * lr;
            *(float2*)(sAcc + lrA * ACC_STRIDE + col) = make_float2(acc[nt][0], acc[nt][1]);
            *(float2*)(sAcc + lrB * ACC_STRIDE + col) = make_float2(acc[nt][2], acc[nt][3]);
        }
    }
    __syncthreads();
    if (jh == 0) {
        float lAt = lA + sMax[1][lrA];
        float lBt = lB + sMax[1][lrB];
        const float liA = 1.f / lAt, liB = 1.f / lBt;
        const float* vs = g_vsum + bh * DD;
        float* xA = out_x + ((size_t)bh * SS + rowA) * DD;
        float* xB = out_x + ((size_t)bh * SS + rowB) * DD;
        #pragma unroll
        for (int nt = 0; nt < 8; nt++) {
            int col = nt * 8 + 2 * lr;
            float2 pA = *(float2*)(sAcc + lrA * ACC_STRIDE + col);
            float2 pB = *(float2*)(sAcc + lrB * ACC_STRIDE + col);
            float a0, a1, b0, b1;
            if (rvA) { a0 = (acc[nt][0] + pA.x) * liA; a1 = (acc[nt][1] + pA.y) * liA; }
            else     { a0 = vs[col] * inv2048; a1 = vs[col + 1] * inv2048; }
            if (rvB) { b0 = (acc[nt][2] + pB.x) * liB; b1 = (acc[nt][3] + pB.y) * liB; }
            else     { b0 = vs[col] * inv2048; b1 = vs[col + 1] * inv2048; }
            *(float2*)(xA + col) = make_float2(a0, a1);
            *(float2*)(xB + col) = make_float2(b0, b1);
        }
    }
}

extern "C" void kernel_launch(void* const* d_in, const int* in_sizes, int n_in,
                              void* d_out, int out_size) {
    const float* qkv     = (const float*)d_in[0];
    const float* cosb    = (const float*)d_in[1];
    const float* sinb    = (const float*)d_in[2];
    const int*   seqlens = (const int*)d_in[3];

    float* out        = (float*)d_out;
    float* out_x      = out;                                 // [B,H,S,D]
    float* out_logits = out + (size_t)BB * HH * SS * DD;     // [B,H,S,S]

    const int total_qk = BB * SS * 2 * HH * 32;
    rotary_qk_kernel<<<(total_qk + 255) / 256, 256>>>(qkv, cosb, sinb);
    vtrans_kernel<<<dim3(SS / 64, BH), 256>>>(qkv);
    vsum_kernel<<<BH, 256>>>();

    cudaFuncSetAttribute(attn_kernel,
                         cudaFuncAttributeMaxDynamicSharedMemorySize, SMEM_DYN);
    attn_kernel<<<dim3(SS / TI, BH), NTH, SMEM_DYN>>>(seqlens, out_x, out_logits);
}

// round 8
// speedup vs baseline: 1.0038x; 1.0038x over previous
#include <cuda_runtime.h>
#include <cuda_bf16.h>
#include <cuda_fp16.h>
#include <math.h>
#include <stdint.h>

#define BB 2
#define SS 2048
#define HH 12
#define DD 64
#define BH (BB*HH)

#define TI 128
#define TJ 64
#define NTH 512

#define NELEM (BB*HH*SS*DD)
__device__ __nv_bfloat16 g_qh[NELEM], g_ql[NELEM];   // [bh][s][d]
__device__ __nv_bfloat16 g_kh[NELEM], g_kl[NELEM];   // [bh][s][d]
__device__ __half        g_vt[NELEM];                // [bh][d][s]
__device__ float         g_vsum[BH * DD];

// smem layout: padded rows of 72 elems (144 B)
#define ROWB 144
#define OQH 0                      // 128 x ROWB = 18432
#define OQL 18432
#define OBUF 36864                 // two 27648-byte K/V buffers
#define BKH 0
#define BKL 9216
#define BV  18432
#define BUF_BYTES 27648
#define SMEM_DYN (OBUF + 2 * BUF_BYTES)   // 92160
#define ACC_STRIDE 66

// ---------------------------------------------------------------------------
__device__ __forceinline__ void mma_bf16(float (&c)[4], const uint32_t* a,
                                         uint32_t b0, uint32_t b1) {
    asm volatile(
        "mma.sync.aligned.m16n8k16.row.col.f32.bf16.bf16.f32 "
        "{%0,%1,%2,%3}, {%4,%5,%6,%7}, {%8,%9}, {%0,%1,%2,%3};\n"
        : "+f"(c[0]), "+f"(c[1]), "+f"(c[2]), "+f"(c[3])
        : "r"(a[0]), "r"(a[1]), "r"(a[2]), "r"(a[3]), "r"(b0), "r"(b1));
}
__device__ __forceinline__ void mma_fp16(float (&c)[4], const uint32_t* a,
                                         uint32_t b0, uint32_t b1) {
    asm volatile(
        "mma.sync.aligned.m16n8k16.row.col.f32.f16.f16.f32 "
        "{%0,%1,%2,%3}, {%4,%5,%6,%7}, {%8,%9}, {%0,%1,%2,%3};\n"
        : "+f"(c[0]), "+f"(c[1]), "+f"(c[2]), "+f"(c[3])
        : "r"(a[0]), "r"(a[1]), "r"(a[2]), "r"(a[3]), "r"(b0), "r"(b1));
}

#define LDSM4(r0, r1, r2, r3, addr) \
    asm volatile("ldmatrix.sync.aligned.m8n8.x4.shared.b16 {%0,%1,%2,%3}, [%4];" \
        : "=r"(r0), "=r"(r1), "=r"(r2), "=r"(r3) : "r"(addr))

#define CP16(dst, src) \
    asm volatile("cp.async.cg.shared.global [%0], [%1], 16;" \
        :: "r"(dst), "l"(src) : "memory")
#define CP_COMMIT() asm volatile("cp.async.commit_group;" ::: "memory")
#define CP_WAIT(n)  asm volatile("cp.async.wait_group %0;" :: "n"(n) : "memory")

__device__ __forceinline__ uint32_t smem_u32(const void* p) {
    uint32_t a;
    asm("{ .reg .u64 t; cvta.to.shared.u64 t, %1; cvt.u32.u64 %0, t; }" : "=r"(a) : "l"(p));
    return a;
}
__device__ __forceinline__ uint32_t pack_half2(float lo, float hi) {
    __half2 t = __floats2half2_rn(lo, hi);
    return *(uint32_t*)&t;
}

// ---------------------------------------------------------------------------
__global__ void rotary_qk_kernel(const float* __restrict__ qkv,
                                 const float* __restrict__ cosb,
                                 const float* __restrict__ sinb) {
    int idx = blockIdx.x * blockDim.x + threadIdx.x;
    const int total = BB * SS * 2 * HH * 32;
    if (idx >= total) return;
    int d2 = idx & 31; int rest = idx >> 5;
    int h = rest % HH; rest /= HH;
    int t = rest & 1;  rest >>= 1;
    int s = rest % SS; int b = rest / SS;

    size_t qoff = ((((size_t)b * SS + s) * 3 + t) * HH + h) * DD + d2;
    float x1 = qkv[qoff];
    float x2 = qkv[qoff + 32];
    int coff = (s * 3 + t) * DD + d2;
    float c = cosb[coff], sn = sinb[coff];
    float o1 = x1 * c - x2 * sn;
    float o2 = x2 * c + x1 * sn;

    __nv_bfloat16 h1 = __float2bfloat16_rn(o1);
    __nv_bfloat16 l1 = __float2bfloat16_rn(o1 - __bfloat162float(h1));
    __nv_bfloat16 h2 = __float2bfloat16_rn(o2);
    __nv_bfloat16 l2 = __float2bfloat16_rn(o2 - __bfloat162float(h2));

    __nv_bfloat16* dh = (t == 0) ? g_qh : g_kh;
    __nv_bfloat16* dl = (t == 0) ? g_ql : g_kl;
    size_t doff = (((size_t)b * HH + h) * SS + s) * DD + d2;
    dh[doff] = h1; dh[doff + 32] = h2;
    dl[doff] = l1; dl[doff + 32] = l2;
}

// ---------------------------------------------------------------------------
__global__ void vtrans_kernel(const float* __restrict__ qkv) {
    __shared__ __half sT[64 * 72];
    const int bh = blockIdx.y;
    const int b = bh / HH, h = bh % HH;
    const int s0 = blockIdx.x * 64;
    const int tid = threadIdx.x;
    const int sl = tid >> 2;
    const int d2b = (tid & 3) * 8;
    const int s = s0 + sl;

    const float* base = qkv + (((size_t)(b * SS + s) * 3 + 2) * HH + h) * DD;
    #pragma unroll
    for (int i = 0; i < 8; i++) {
        int d = d2b + i;
        sT[d * 72 + sl]        = __float2half_rn(base[d]);
        sT[(d + 32) * 72 + sl] = __float2half_rn(base[d + 32]);
    }
    __syncthreads();
    #pragma unroll
    for (int c = tid; c < 512; c += 256) {
        int r = c >> 3, co = (c & 7) * 8;
        size_t dst = ((size_t)bh * DD + r) * SS + s0 + co;
        *(uint4*)(g_vt + dst) = *(const uint4*)(sT + r * 72 + co);
    }
}

// ---------------------------------------------------------------------------
__global__ void vsum_kernel() {
    const int bh = blockIdx.x;
    const int tid = threadIdx.x;
    const int d = tid >> 2;
    const int q = tid & 3;
    const __half* src = g_vt + ((size_t)bh * DD + d) * SS + q * 512;
    float s = 0.f;
    #pragma unroll 8
    for (int i = 0; i < 64; i++) {
        uint4 v = *(const uint4*)(src + i * 8);
        const __half2* h2 = (const __half2*)&v;
        #pragma unroll
        for (int k = 0; k < 4; k++) {
            float2 f = __half22float2(h2[k]);
            s += f.x + f.y;
        }
    }
    s += __shfl_xor_sync(0xffffffffu, s, 1);
    s += __shfl_xor_sync(0xffffffffu, s, 2);
    if (q == 0) g_vsum[bh * DD + d] = s;
}

// ---------------------------------------------------------------------------
// flash attention, 512 threads: warp (rg, jh) does 16 rows x 32 j-cols
// ---------------------------------------------------------------------------
__global__ void __launch_bounds__(NTH, 1)
attn_kernel(const int* __restrict__ seqlens,
            float* __restrict__ out_x,
            float* __restrict__ out_logits) {
    extern __shared__ char smem[];
    const uint32_t sb = smem_u32(smem);
    __shared__ float sMax[2][128];

    const int tid = threadIdx.x;
    const int wid = tid >> 5;
    const int lane = tid & 31;
    const int lq = lane >> 2;
    const int lr = lane & 3;
    const int rg = wid & 7;          // row group: rows rg*16 .. +16
    const int jh = wid >> 3;         // j-half: cols jh*32 .. +32

    const int bh = blockIdx.y;
    const int b = bh / HH;
    const int i0 = blockIdx.x * TI;
    const int seqlen = seqlens[b];
    const float inv2048 = 1.0f / 2048.0f;

    // ---------- fully-masked i-tile ----------
    if (i0 >= seqlen) {
        float4 fill = make_float4(-1e10f, -1e10f, -1e10f, -1e10f);
        float4* lg = (float4*)(out_logits + ((size_t)bh * SS + i0) * SS);
        #pragma unroll 4
        for (int c = tid; c < TI * SS / 4; c += NTH)
            lg[c] = fill;
        const float* vs = g_vsum + bh * DD;
        float4* xo = (float4*)(out_x + ((size_t)bh * SS + i0) * DD);
        for (int c = tid; c < TI * DD / 4; c += NTH) {
            int dcol = (c & 15) * 4;
            xo[c] = make_float4(vs[dcol] * inv2048, vs[dcol + 1] * inv2048,
                                vs[dcol + 2] * inv2048, vs[dcol + 3] * inv2048);
        }
        return;
    }

    const int jtmax = (seqlen + TJ - 1) / TJ;
    const size_t bh_off = (size_t)bh * SS * DD;
    const size_t v_off = (size_t)bh * DD * SS;

    const uint32_t lmo = (uint32_t)(lane & 7) * ROWB + (uint32_t)((lane >> 3) & 3) * 16;

    // ---- stage Q (hi/lo) into smem ----
    {
        const __nv_bfloat16* qh = g_qh + bh_off + (size_t)i0 * DD;
        const __nv_bfloat16* ql = g_ql + bh_off + (size_t)i0 * DD;
        #pragma unroll
        for (int c = tid; c < 1024; c += NTH) {
            int r = c >> 3, co = (c & 7) * 8;
            *(uint4*)(smem + OQH + r * ROWB + co * 2) = *(const uint4*)(qh + r * DD + co);
            *(uint4*)(smem + OQL + r * ROWB + co * 2) = *(const uint4*)(ql + r * DD + co);
        }
    }

    // ---- prefetch (1 chunk per array per thread) ----
    #define ISSUE_PREFETCH(JT, BUF) do { \
        uint32_t bba = sb + OBUF + (BUF) * BUF_BYTES; \
        const __nv_bfloat16* _kh = g_kh + bh_off + (size_t)(JT) * TJ * DD; \
        const __nv_bfloat16* _kl = g_kl + bh_off + (size_t)(JT) * TJ * DD; \
        const __half* _v = g_vt + v_off + (size_t)(JT) * TJ; \
        int c = tid; \
        int r = c >> 3, co = (c & 7) * 8; \
        uint32_t dof = (uint32_t)r * ROWB + co * 2; \
        CP16(bba + BKH + dof, _kh + r * DD + co); \
        CP16(bba + BKL + dof, _kl + r * DD + co); \
        CP16(bba + BV + dof, _v + (size_t)r * SS + co); \
        CP_COMMIT(); \
    } while (0)

    ISSUE_PREFETCH(0, 0);
    __syncthreads();   // Q smem visible for ldmatrix

    // ---- loop-invariant Q a-frags via ldmatrix ----
    uint32_t aQh[16], aQl[16];
    {
        const uint32_t qlmo = ((uint32_t)(lane & 7) + ((uint32_t)(lane >> 3) & 1) * 8) * ROWB
                            + ((uint32_t)(lane >> 4)) * 16;
        uint32_t qb0 = sb + OQH + (uint32_t)rg * 16 * ROWB + qlmo;
        uint32_t qb1 = sb + OQL + (uint32_t)rg * 16 * ROWB + qlmo;
        #pragma unroll
        for (int kt = 0; kt < 4; kt++) {
            LDSM4(aQh[kt*4+0], aQh[kt*4+1], aQh[kt*4+2], aQh[kt*4+3], qb0 + kt * 32);
            LDSM4(aQl[kt*4+0], aQl[kt*4+1], aQl[kt*4+2], aQl[kt*4+3], qb1 + kt * 32);
        }
    }

    const int rowA = i0 + rg * 16 + lq;
    const int rowB = rowA + 8;
    const bool rvA = rowA < seqlen;
    const bool rvB = rowB < seqlen;
    const int lrA = rg * 16 + lq;       // local row indices
    const int lrB = lrA + 8;

    float mA = -INFINITY, mB = -INFINITY, lA = 0.f, lB = 0.f;
    float acc[8][4];
    #pragma unroll
    for (int n = 0; n < 8; n++)
        #pragma unroll
        for (int q = 0; q < 4; q++) acc[n][q] = 0.f;

    float* lgA = out_logits + ((size_t)bh * SS + rowA) * SS;
    float* lgB = out_logits + ((size_t)bh * SS + rowB) * SS;

    for (int jt = 0; jt < jtmax; jt++) {
        if (jt + 1 < jtmax) {
            ISSUE_PREFETCH(jt + 1, (jt + 1) & 1);
            CP_WAIT(1);
        } else {
            CP_WAIT(0);
        }
        __syncthreads();

        const uint32_t bba = sb + OBUF + (jt & 1) * BUF_BYTES;
        const uint32_t uKh = bba + BKH, uKl = bba + BKL, uVh = bba + BV;

        // ---- S = Q K^T over this warp's 32 j-cols (3-product bf16) ----
        float s[4][4];
        #pragma unroll
        for (int nt = 0; nt < 4; nt++) {
            #pragma unroll
            for (int q = 0; q < 4; q++) s[nt][q] = 0.f;
            uint32_t kb[8], lb[8];
            uint32_t a0 = uKh + ((uint32_t)jh * 32 + nt * 8) * ROWB + lmo;
            uint32_t a1 = uKl + ((uint32_t)jh * 32 + nt * 8) * ROWB + lmo;
            LDSM4(kb[0], kb[1], kb[2], kb[3], a0);
            LDSM4(kb[4], kb[5], kb[6], kb[7], a0 + 64);
            LDSM4(lb[0], lb[1], lb[2], lb[3], a1);
            LDSM4(lb[4], lb[5], lb[6], lb[7], a1 + 64);
            #pragma unroll
            for (int kt = 0; kt < 4; kt++) {
                mma_bf16(s[nt], aQh + kt * 4, kb[2*kt], kb[2*kt+1]);
                mma_bf16(s[nt], aQl + kt * 4, kb[2*kt], kb[2*kt+1]);
                mma_bf16(s[nt], aQh + kt * 4, lb[2*kt], lb[2*kt+1]);
            }
        }

        // ---- scale + mask + stream logits ----
        const int jb = jt * TJ + jh * 32;
        #pragma unroll
        for (int nt = 0; nt < 4; nt++) {
            int col = jb + nt * 8 + 2 * lr;
            bool c0v = col < seqlen;
            bool c1v = (col + 1) < seqlen;
            float v0 = (rvA && c0v) ? s[nt][0] * 0.125f : -1e10f;
            float v1 = (rvA && c1v) ? s[nt][1] * 0.125f : -1e10f;
            float v2 = (rvB && c0v) ? s[nt][2] * 0.125f : -1e10f;
            float v3 = (rvB && c1v) ? s[nt][3] * 0.125f : -1e10f;
            *(float2*)(lgA + col) = make_float2(v0, v1);
            *(float2*)(lgB + col) = make_float2(v2, v3);
            s[nt][0] = v0; s[nt][1] = v1; s[nt][2] = v2; s[nt][3] = v3;
        }

        // ---- row max: quad reduce + cross-half exchange ----
        float tmA = -INFINITY, tmB = -INFINITY;
        #pragma unroll
        for (int nt = 0; nt < 4; nt++) {
            tmA = fmaxf(tmA, fmaxf(s[nt][0], s[nt][1]));
            tmB = fmaxf(tmB, fmaxf(s[nt][2], s[nt][3]));
        }
        tmA = fmaxf(tmA, __shfl_xor_sync(0xffffffffu, tmA, 1));
        tmA = fmaxf(tmA, __shfl_xor_sync(0xffffffffu, tmA, 2));
        tmB = fmaxf(tmB, __shfl_xor_sync(0xffffffffu, tmB, 1));
        tmB = fmaxf(tmB, __shfl_xor_sync(0xffffffffu, tmB, 2));
        if (lr == 0) {
            sMax[jh][lrA] = tmA;
            sMax[jh][lrB] = tmB;
        }
        __syncthreads();
        tmA = fmaxf(tmA, sMax[1 - jh][lrA]);
        tmB = fmaxf(tmB, sMax[1 - jh][lrB]);

        float mnA = fmaxf(mA, tmA), mnB = fmaxf(mB, tmB);
        float fA = __expf(mA - mnA), fB = __expf(mB - mnB);
        mA = mnA; mB = mnB;

        float sumA = 0.f, sumB = 0.f;
        #pragma unroll
        for (int nt = 0; nt < 4; nt++) {
            s[nt][0] = __expf(s[nt][0] - mnA);
            s[nt][1] = __expf(s[nt][1] - mnA);
            s[nt][2] = __expf(s[nt][2] - mnB);
            s[nt][3] = __expf(s[nt][3] - mnB);
            sumA += s[nt][0] + s[nt][1];
            sumB += s[nt][2] + s[nt][3];
        }
        sumA += __shfl_xor_sync(0xffffffffu, sumA, 1);
        sumA += __shfl_xor_sync(0xffffffffu, sumA, 2);
        sumB += __shfl_xor_sync(0xffffffffu, sumB, 1);
        sumB += __shfl_xor_sync(0xffffffffu, sumB, 2);
        lA = lA * fA + sumA;     // own half only; combined at end
        lB = lB * fB + sumB;

        #pragma unroll
        for (int nt = 0; nt < 8; nt++) {
            acc[nt][0] *= fA; acc[nt][1] *= fA;
            acc[nt][2] *= fB; acc[nt][3] *= fB;
        }

        // ---- pack P (own 32 j) into fp16 a-frags ----
        uint32_t aP[8];
        #pragma unroll
        for (int kt = 0; kt < 2; kt++) {
            #pragma unroll
            for (int g = 0; g < 4; g++) {
                int nt = 2 * kt + (g >> 1);
                float p0 = s[nt][(g & 1) ? 2 : 0];
                float p1 = s[nt][(g & 1) ? 3 : 1];
                aP[kt * 4 + g] = pack_half2(p0, p1);
            }
        }

        // ---- X += P V : own j-half, full d (8 d-chunks) ----
        #pragma unroll
        for (int nt = 0; nt < 8; nt++) {
            uint32_t vb[4];
            uint32_t a0 = uVh + (uint32_t)nt * (8 * ROWB) + (uint32_t)jh * 64 + lmo;
            LDSM4(vb[0], vb[1], vb[2], vb[3], a0);
            mma_fp16(acc[nt], aP, vb[0], vb[1]);
            mma_fp16(acc[nt], aP + 4, vb[2], vb[3]);
        }
        __syncthreads();
    }

    // ---- tail fill: logits cols [jtmax*TJ, SS) ----
    {
        const int ctail = SS - jtmax * TJ;
        if (ctail > 0) {
            float4 fill = make_float4(-1e10f, -1e10f, -1e10f, -1e10f);
            float* base = out_logits + ((size_t)bh * SS + i0) * SS + jtmax * TJ;
            const int c4 = ctail / 4;
            for (int c = tid; c < TI * c4; c += NTH) {
                int r = c / c4, cc = (c % c4) * 4;
                *(float4*)(base + (size_t)r * SS + cc) = fill;
            }
        }
    }

    // ---- cross-half combine: l and acc ----
    float* sAcc = (float*)(smem + OBUF);    // 128 x ACC_STRIDE floats (33.8 KB)
    if (lr == 0) {
        sMax[jh][lrA] = lA;
        sMax[jh][lrB] = lB;
    }
    if (jh == 1) {
        #pragma unroll
        for (int nt = 0; nt < 8; nt++) {
            int col = nt * 8 + 2 * lr;
            *(float2*)(sAcc + lrA * ACC_STRIDE + col) = make_float2(acc[nt][0], acc[nt][1]);
            *(float2*)(sAcc + lrB * ACC_STRIDE + col) = make_float2(acc[nt][2], acc[nt][3]);
        }
    }
    __syncthreads();
    if (jh == 0) {
        float lAt = lA + sMax[1][lrA];
        float lBt = lB + sMax[1][lrB];
        const float liA = 1.f / lAt, liB = 1.f / lBt;
        const float* vs = g_vsum + bh * DD;
        float* xA = out_x + ((size_t)bh * SS + rowA) * DD;
        float* xB = out_x + ((size_t)bh * SS + rowB) * DD;
        #pragma unroll
        for (int nt = 0; nt < 8; nt++) {
            int col = nt * 8 + 2 * lr;
            float2 pA = *(float2*)(sAcc + lrA * ACC_STRIDE + col);
            float2 pB = *(float2*)(sAcc + lrB * ACC_STRIDE + col);
            float a0, a1, b0, b1;
            if (rvA) { a0 = (acc[nt][0] + pA.x) * liA; a1 = (acc[nt][1] + pA.y) * liA; }
            else     { a0 = vs[col] * inv2048; a1 = vs[col + 1] * inv2048; }
            if (rvB) { b0 = (acc[nt][2] + pB.x) * liB; b1 = (acc[nt][3] + pB.y) * liB; }
            else     { b0 = vs[col] * inv2048; b1 = vs[col + 1] * inv2048; }
            *(float2*)(xA + col) = make_float2(a0, a1);
            *(float2*)(xB + col) = make_float2(b0, b1);
        }
    }
}

extern "C" void kernel_launch(void* const* d_in, const int* in_sizes, int n_in,
                              void* d_out, int out_size) {
    const float* qkv     = (const float*)d_in[0];
    const float* cosb    = (const float*)d_in[1];
    const float* sinb    = (const float*)d_in[2];
    const int*   seqlens = (const int*)d_in[3];

    float* out        = (float*)d_out;
    float* out_x      = out;                                 // [B,H,S,D]
    float* out_logits = out + (size_t)BB * HH * SS * DD;     // [B,H,S,S]

    const int total_qk = BB * SS * 2 * HH * 32;
    rotary_qk_kernel<<<(total_qk + 255) / 256, 256>>>(qkv, cosb, sinb);
    vtrans_kernel<<<dim3(SS / 64, BH), 256>>>(qkv);
    vsum_kernel<<<BH, 256>>>();

    cudaFuncSetAttribute(attn_kernel,
                         cudaFuncAttributeMaxDynamicSharedMemorySize, SMEM_DYN);
    attn_kernel<<<dim3(SS / TI, BH), NTH, SMEM_DYN>>>(seqlens, out_x, out_logits);
}

// round 9
// speedup vs baseline: 1.1693x; 1.1650x over previous
#include <cuda_runtime.h>
#include <cuda_bf16.h>
#include <cuda_fp16.h>
#include <math.h>
#include <stdint.h>

#define BB 2
#define SS 2048
#define HH 12
#define DD 64
#define BH (BB*HH)

#define TI 128
#define TJ 64
#define NTHREADS 256
#define NITILE (SS/TI)          // 16
#define NTASKS (BH*NITILE)      // 384
#define WORKERS 152

#define NELEM (BB*HH*SS*DD)
__device__ __nv_bfloat16 g_qh[NELEM], g_ql[NELEM];   // [bh][s][d]
__device__ __nv_bfloat16 g_kh[NELEM], g_kl[NELEM];   // [bh][s][d]
__device__ __half        g_vt[NELEM];                // [bh][d][s]
__device__ float         g_vsum[BH * DD];
__device__ int           g_task;

// smem tile layout: padded rows of 72 elems (144 B); 64 rows = 9216 B per array
#define ROWB 144
#define OKH 0
#define OKL 9216
#define OVH 18432
#define BUF_BYTES 27648
#define SMEM_DYN (2 * BUF_BYTES)

// ---------------------------------------------------------------------------
__device__ __forceinline__ void mma_bf16(float (&c)[4], const uint32_t* a,
                                         uint32_t b0, uint32_t b1) {
    asm volatile(
        "mma.sync.aligned.m16n8k16.row.col.f32.bf16.bf16.f32 "
        "{%0,%1,%2,%3}, {%4,%5,%6,%7}, {%8,%9}, {%0,%1,%2,%3};\n"
        : "+f"(c[0]), "+f"(c[1]), "+f"(c[2]), "+f"(c[3])
        : "r"(a[0]), "r"(a[1]), "r"(a[2]), "r"(a[3]), "r"(b0), "r"(b1));
}
__device__ __forceinline__ void mma_fp16(float (&c)[4], const uint32_t* a,
                                         uint32_t b0, uint32_t b1) {
    asm volatile(
        "mma.sync.aligned.m16n8k16.row.col.f32.f16.f16.f32 "
        "{%0,%1,%2,%3}, {%4,%5,%6,%7}, {%8,%9}, {%0,%1,%2,%3};\n"
        : "+f"(c[0]), "+f"(c[1]), "+f"(c[2]), "+f"(c[3])
        : "r"(a[0]), "r"(a[1]), "r"(a[2]), "r"(a[3]), "r"(b0), "r"(b1));
}

#define LDSM4(r0, r1, r2, r3, addr) \
    asm volatile("ldmatrix.sync.aligned.m8n8.x4.shared.b16 {%0,%1,%2,%3}, [%4];" \
        : "=r"(r0), "=r"(r1), "=r"(r2), "=r"(r3) : "r"(addr))

#define CP16(dst, src) \
    asm volatile("cp.async.cg.shared.global [%0], [%1], 16;" \
        :: "r"(dst), "l"(src) : "memory")
#define CP_COMMIT() asm volatile("cp.async.commit_group;" ::: "memory")
#define CP_WAIT(n)  asm volatile("cp.async.wait_group %0;" :: "n"(n) : "memory")

__device__ __forceinline__ uint32_t smem_u32(const void* p) {
    uint32_t a;
    asm("{ .reg .u64 t; cvta.to.shared.u64 t, %1; cvt.u32.u64 %0, t; }" : "=r"(a) : "l"(p));
    return a;
}
__device__ __forceinline__ uint32_t pack_half2(float lo, float hi) {
    __half2 t = __floats2half2_rn(lo, hi);
    return *(uint32_t*)&t;
}

// ---------------------------------------------------------------------------
__global__ void rotary_qk_kernel(const float* __restrict__ qkv,
                                 const float* __restrict__ cosb,
                                 const float* __restrict__ sinb) {
    int idx = blockIdx.x * blockDim.x + threadIdx.x;
    const int total = BB * SS * 2 * HH * 32;
    if (idx >= total) return;
    int d2 = idx & 31; int rest = idx >> 5;
    int h = rest % HH; rest /= HH;
    int t = rest & 1;  rest >>= 1;
    int s = rest % SS; int b = rest / SS;

    size_t qoff = ((((size_t)b * SS + s) * 3 + t) * HH + h) * DD + d2;
    float x1 = qkv[qoff];
    float x2 = qkv[qoff + 32];
    int coff = (s * 3 + t) * DD + d2;
    float c = cosb[coff], sn = sinb[coff];
    float o1 = x1 * c - x2 * sn;
    float o2 = x2 * c + x1 * sn;

    __nv_bfloat16 h1 = __float2bfloat16_rn(o1);
    __nv_bfloat16 l1 = __float2bfloat16_rn(o1 - __bfloat162float(h1));
    __nv_bfloat16 h2 = __float2bfloat16_rn(o2);
    __nv_bfloat16 l2 = __float2bfloat16_rn(o2 - __bfloat162float(h2));

    __nv_bfloat16* dh = (t == 0) ? g_qh : g_kh;
    __nv_bfloat16* dl = (t == 0) ? g_ql : g_kl;
    size_t doff = (((size_t)b * HH + h) * SS + s) * DD + d2;
    dh[doff] = h1; dh[doff + 32] = h2;
    dl[doff] = l1; dl[doff + 32] = l2;
}

// ---------------------------------------------------------------------------
__global__ void vtrans_kernel(const float* __restrict__ qkv) {
    __shared__ __half sT[64 * 72];
    const int bh = blockIdx.y;
    const int b = bh / HH, h = bh % HH;
    const int s0 = blockIdx.x * 64;
    const int tid = threadIdx.x;
    const int sl = tid >> 2;
    const int d2b = (tid & 3) * 8;
    const int s = s0 + sl;

    const float* base = qkv + (((size_t)(b * SS + s) * 3 + 2) * HH + h) * DD;
    #pragma unroll
    for (int i = 0; i < 8; i++) {
        int d = d2b + i;
        sT[d * 72 + sl]        = __float2half_rn(base[d]);
        sT[(d + 32) * 72 + sl] = __float2half_rn(base[d + 32]);
    }
    __syncthreads();
    #pragma unroll
    for (int c = tid; c < 512; c += 256) {
        int r = c >> 3, co = (c & 7) * 8;
        size_t dst = ((size_t)bh * DD + r) * SS + s0 + co;
        *(uint4*)(g_vt + dst) = *(const uint4*)(sT + r * 72 + co);
    }
}

// ---------------------------------------------------------------------------
// vsum + task-counter reset (stream-ordered before attn)
// ---------------------------------------------------------------------------
__global__ void vsum_kernel() {
    if (blockIdx.x == 0 && threadIdx.x == 0) g_task = 0;
    const int bh = blockIdx.x;
    const int tid = threadIdx.x;
    const int d = tid >> 2;
    const int q = tid & 3;
    const __half* src = g_vt + ((size_t)bh * DD + d) * SS + q * 512;
    float s = 0.f;
    #pragma unroll 8
    for (int i = 0; i < 64; i++) {
        uint4 v = *(const uint4*)(src + i * 8);
        const __half2* h2 = (const __half2*)&v;
        #pragma unroll
        for (int k = 0; k < 4; k++) {
            float2 f = __half22float2(h2[k]);
            s += f.x + f.y;
        }
    }
    s += __shfl_xor_sync(0xffffffffu, s, 1);
    s += __shfl_xor_sync(0xffffffffu, s, 2);
    if (q == 0) g_vsum[bh * DD + d] = s;
}

// ---------------------------------------------------------------------------
// persistent flash attention, dynamic LPT task queue
// ---------------------------------------------------------------------------
__global__ void __launch_bounds__(NTHREADS, 1)
attn_kernel(const int* __restrict__ seqlens,
            float* __restrict__ out_x,
            float* __restrict__ out_logits) {
    extern __shared__ char smem[];
    const uint32_t sb = smem_u32(smem);
    __shared__ int sTask;

    const int tid = threadIdx.x;
    const int wid = tid >> 5;
    const int lane = tid & 31;
    const int lq = lane >> 2;
    const int lr = lane & 3;

    const int sl0 = seqlens[0];
    const int sl1 = seqlens[1];
    // LPT ordering: valid tasks of longer batch, valid of shorter, then masked
    const int bA = (sl0 >= sl1) ? 0 : 1;
    const int bBt = 1 - bA;
    const int slA = (bA == 0) ? sl0 : sl1;
    const int slB = (bA == 0) ? sl1 : sl0;
    const int ivA = (slA + TI - 1) / TI;        // valid i-tiles, <= 16
    const int ivB = (slB + TI - 1) / TI;
    const int nA = HH * ivA;
    const int nB = HH * ivB;
    const int mA = HH * (NITILE - ivA);

    const float inv2048 = 1.0f / 2048.0f;
    const uint32_t lmo = (uint32_t)(lane & 7) * ROWB + (uint32_t)((lane >> 3) & 3) * 16;

    for (;;) {
        if (tid == 0) sTask = atomicAdd(&g_task, 1);
        __syncthreads();
        const int t = sTask;
        if (t >= NTASKS) break;

        // ---- decode task -> (b, h, i-tile) ----
        int b, h, it;
        if (t < nA)            { b = bA;  h = t % HH;  it = t / HH; }
        else if (t < nA + nB)  { int u = t - nA; b = bBt; h = u % HH; it = u / HH; }
        else {
            int u = t - nA - nB;
            if (u < mA) { b = bA;  h = u % HH; it = ivA + u / HH; }
            else        { u -= mA; b = bBt; h = u % HH; it = ivB + u / HH; }
        }
        const int bh = b * HH + h;
        const int i0 = it * TI;
        const int seqlen = (b == 0) ? sl0 : sl1;

        // ---------- fully-masked i-tile: pure fill ----------
        if (i0 >= seqlen) {
            float4 fill = make_float4(-1e10f, -1e10f, -1e10f, -1e10f);
            float4* lg = (float4*)(out_logits + ((size_t)bh * SS + i0) * SS);
            #pragma unroll 8
            for (int c = tid; c < TI * SS / 4; c += NTHREADS)
                lg[c] = fill;
            const float* vs = g_vsum + bh * DD;
            float4* xo = (float4*)(out_x + ((size_t)bh * SS + i0) * DD);
            for (int c = tid; c < TI * DD / 4; c += NTHREADS) {
                int dcol = (c & 15) * 4;
                xo[c] = make_float4(vs[dcol] * inv2048, vs[dcol + 1] * inv2048,
                                    vs[dcol + 2] * inv2048, vs[dcol + 3] * inv2048);
            }
            continue;   // barrier at loop top isolates smem reuse
        }

        const int jtmax = (seqlen + TJ - 1) / TJ;
        const size_t bh_off = (size_t)bh * SS * DD;
        const size_t v_off = (size_t)bh * DD * SS;

        // ---- persistent Q fragments (hi/lo) from gmem ----
        uint32_t aQh[16], aQl[16];
        {
            const __nv_bfloat16* q0 = g_qh + bh_off + (size_t)(i0 + wid * 16 + lq) * DD + 2 * lr;
            const __nv_bfloat16* q1 = g_ql + bh_off + (size_t)(i0 + wid * 16 + lq) * DD + 2 * lr;
            #pragma unroll
            for (int kt = 0; kt < 4; kt++) {
                aQh[kt*4+0] = *(const uint32_t*)(q0 + kt * 16);
                aQh[kt*4+1] = *(const uint32_t*)(q0 + 8 * DD + kt * 16);
                aQh[kt*4+2] = *(const uint32_t*)(q0 + kt * 16 + 8);
                aQh[kt*4+3] = *(const uint32_t*)(q0 + 8 * DD + kt * 16 + 8);
                aQl[kt*4+0] = *(const uint32_t*)(q1 + kt * 16);
                aQl[kt*4+1] = *(const uint32_t*)(q1 + 8 * DD + kt * 16);
                aQl[kt*4+2] = *(const uint32_t*)(q1 + kt * 16 + 8);
                aQl[kt*4+3] = *(const uint32_t*)(q1 + 8 * DD + kt * 16 + 8);
            }
        }

        const int rowA = i0 + wid * 16 + lq;
        const int rowB = rowA + 8;
        const bool rvA = rowA < seqlen;
        const bool rvB = rowB < seqlen;

        float mA_ = -INFINITY, mB_ = -INFINITY, lA = 0.f, lB = 0.f;
        float acc[8][4];
        #pragma unroll
        for (int n = 0; n < 8; n++)
            #pragma unroll
            for (int q = 0; q < 4; q++) acc[n][q] = 0.f;

        float* lgA = out_logits + ((size_t)bh * SS + rowA) * SS;
        float* lgB = out_logits + ((size_t)bh * SS + rowB) * SS;

        #define ISSUE_PREFETCH(JT, BUF) do { \
            uint32_t bba = sb + (BUF) * BUF_BYTES; \
            const __nv_bfloat16* _kh = g_kh + bh_off + (size_t)(JT) * TJ * DD; \
            const __nv_bfloat16* _kl = g_kl + bh_off + (size_t)(JT) * TJ * DD; \
            const __half* _v = g_vt + v_off + (size_t)(JT) * TJ; \
            _Pragma("unroll") \
            for (int c = tid; c < 512; c += NTHREADS) { \
                int r = c >> 3, co = (c & 7) * 8; \
                uint32_t dof = (uint32_t)r * ROWB + co * 2; \
                CP16(bba + OKH + dof, _kh + r * DD + co); \
                CP16(bba + OKL + dof, _kl + r * DD + co); \
                CP16(bba + OVH + dof, _v + (size_t)r * SS + co); \
            } \
            CP_COMMIT(); \
        } while (0)

        ISSUE_PREFETCH(0, 0);

        for (int jt = 0; jt < jtmax; jt++) {
            if (jt + 1 < jtmax) {
                ISSUE_PREFETCH(jt + 1, (jt + 1) & 1);
                CP_WAIT(1);
            } else {
                CP_WAIT(0);
            }
            __syncthreads();

            const uint32_t bba = sb + (jt & 1) * BUF_BYTES;
            const uint32_t uKh = bba + OKH, uKl = bba + OKL, uVh = bba + OVH;

            // ---- S = Q K^T (3-product bf16 split) ----
            float s[8][4];
            #pragma unroll
            for (int nt = 0; nt < 8; nt++) {
                #pragma unroll
                for (int q = 0; q < 4; q++) s[nt][q] = 0.f;
                uint32_t kb[8], lb[8];
                uint32_t a0 = uKh + nt * (8 * ROWB) + lmo;
                uint32_t a1 = uKl + nt * (8 * ROWB) + lmo;
                LDSM4(kb[0], kb[1], kb[2], kb[3], a0);
                LDSM4(kb[4], kb[5], kb[6], kb[7], a0 + 64);
                LDSM4(lb[0], lb[1], lb[2], lb[3], a1);
                LDSM4(lb[4], lb[5], lb[6], lb[7], a1 + 64);
                #pragma unroll
                for (int kt = 0; kt < 4; kt++) {
                    mma_bf16(s[nt], aQh + kt * 4, kb[2*kt], kb[2*kt+1]);
                    mma_bf16(s[nt], aQl + kt * 4, kb[2*kt], kb[2*kt+1]);
                    mma_bf16(s[nt], aQh + kt * 4, lb[2*kt], lb[2*kt+1]);
                }
            }

            // ---- scale + mask + stream logits ----
            const int jb = jt * TJ;
            #pragma unroll
            for (int nt = 0; nt < 8; nt++) {
                int col = jb + nt * 8 + 2 * lr;
                bool c0v = col < seqlen;
                bool c1v = (col + 1) < seqlen;
                float v0 = (rvA && c0v) ? s[nt][0] * 0.125f : -1e10f;
                float v1 = (rvA && c1v) ? s[nt][1] * 0.125f : -1e10f;
                float v2 = (rvB && c0v) ? s[nt][2] * 0.125f : -1e10f;
                float v3 = (rvB && c1v) ? s[nt][3] * 0.125f : -1e10f;
                *(float2*)(lgA + col) = make_float2(v0, v1);
                *(float2*)(lgB + col) = make_float2(v2, v3);
                s[nt][0] = v0; s[nt][1] = v1; s[nt][2] = v2; s[nt][3] = v3;
            }

            // ---- online softmax ----
            float tmA = -INFINITY, tmB = -INFINITY;
            #pragma unroll
            for (int nt = 0; nt < 8; nt++) {
                tmA = fmaxf(tmA, fmaxf(s[nt][0], s[nt][1]));
                tmB = fmaxf(tmB, fmaxf(s[nt][2], s[nt][3]));
            }
            tmA = fmaxf(tmA, __shfl_xor_sync(0xffffffffu, tmA, 1));
            tmA = fmaxf(tmA, __shfl_xor_sync(0xffffffffu, tmA, 2));
            tmB = fmaxf(tmB, __shfl_xor_sync(0xffffffffu, tmB, 1));
            tmB = fmaxf(tmB, __shfl_xor_sync(0xffffffffu, tmB, 2));

            float mnA = fmaxf(mA_, tmA), mnB = fmaxf(mB_, tmB);
            float fA = __expf(mA_ - mnA), fB = __expf(mB_ - mnB);
            mA_ = mnA; mB_ = mnB;

            float sumA = 0.f, sumB = 0.f;
            #pragma unroll
            for (int nt = 0; nt < 8; nt++) {
                s[nt][0] = __expf(s[nt][0] - mnA);
                s[nt][1] = __expf(s[nt][1] - mnA);
                s[nt][2] = __expf(s[nt][2] - mnB);
                s[nt][3] = __expf(s[nt][3] - mnB);
                sumA += s[nt][0] + s[nt][1];
                sumB += s[nt][2] + s[nt][3];
            }
            sumA += __shfl_xor_sync(0xffffffffu, sumA, 1);
            sumA += __shfl_xor_sync(0xffffffffu, sumA, 2);
            sumB += __shfl_xor_sync(0xffffffffu, sumB, 1);
            sumB += __shfl_xor_sync(0xffffffffu, sumB, 2);
            lA = lA * fA + sumA;
            lB = lB * fB + sumB;

            #pragma unroll
            for (int nt = 0; nt < 8; nt++) {
                acc[nt][0] *= fA; acc[nt][1] *= fA;
                acc[nt][2] *= fB; acc[nt][3] *= fB;
            }

            // ---- pack P into fp16 a-frags ----
            uint32_t aP[16];
            #pragma unroll
            for (int kt = 0; kt < 4; kt++) {
                #pragma unroll
                for (int g = 0; g < 4; g++) {
                    int nt = 2 * kt + (g >> 1);
                    float p0 = s[nt][(g & 1) ? 2 : 0];
                    float p1 = s[nt][(g & 1) ? 3 : 1];
                    aP[kt * 4 + g] = pack_half2(p0, p1);
                }
            }

            // ---- X += P V (single fp16 product) ----
            #pragma unroll
            for (int nt = 0; nt < 8; nt++) {
                uint32_t vb[8];
                uint32_t a0 = uVh + nt * (8 * ROWB) + lmo;
                LDSM4(vb[0], vb[1], vb[2], vb[3], a0);
                LDSM4(vb[4], vb[5], vb[6], vb[7], a0 + 64);
                #pragma unroll
                for (int kt = 0; kt < 4; kt++)
                    mma_fp16(acc[nt], aP + kt * 4, vb[2*kt], vb[2*kt+1]);
            }
            __syncthreads();
        }

        // ---- tail fill: logits cols [jtmax*TJ, SS) ----
        {
            const int ctail = SS - jtmax * TJ;
            if (ctail > 0) {
                float4 fill = make_float4(-1e10f, -1e10f, -1e10f, -1e10f);
                float* base = out_logits + ((size_t)bh * SS + i0) * SS + jtmax * TJ;
                const int c4 = ctail / 4;
                for (int c = tid; c < TI * c4; c += NTHREADS) {
                    int r = c / c4, cc = (c % c4) * 4;
                    *(float4*)(base + (size_t)r * SS + cc) = fill;
                }
            }
        }

        // ---- epilogue ----
        const float liA = 1.f / lA, liB = 1.f / lB;
        const float* vs = g_vsum + bh * DD;
        float* xA = out_x + ((size_t)bh * SS + rowA) * DD;
        float* xB = out_x + ((size_t)bh * SS + rowB) * DD;
        #pragma unroll
        for (int nt = 0; nt < 8; nt++) {
            int col = nt * 8 + 2 * lr;
            float a0, a1, b0, b1;
            if (rvA) { a0 = acc[nt][0] * liA; a1 = acc[nt][1] * liA; }
            else     { a0 = vs[col] * inv2048; a1 = vs[col + 1] * inv2048; }
            if (rvB) { b0 = acc[nt][2] * liB; b1 = acc[nt][3] * liB; }
            else     { b0 = vs[col] * inv2048; b1 = vs[col + 1] * inv2048; }
            *(float2*)(xA + col) = make_float2(a0, a1);
            *(float2*)(xB + col) = make_float2(b0, b1);
        }
    }
}

extern "C" void kernel_launch(void* const* d_in, const int* in_sizes, int n_in,
                              void* d_out, int out_size) {
    const float* qkv     = (const float*)d_in[0];
    const float* cosb    = (const float*)d_in[1];
    const float* sinb    = (const float*)d_in[2];
    const int*   seqlens = (const int*)d_in[3];

    float* out        = (float*)d_out;
    float* out_x      = out;                                 // [B,H,S,D]
    float* out_logits = out + (size_t)BB * HH * SS * DD;     // [B,H,S,S]

    const int total_qk = BB * SS * 2 * HH * 32;
    rotary_qk_kernel<<<(total_qk + 255) / 256, 256>>>(qkv, cosb, sinb);
    vtrans_kernel<<<dim3(SS / 64, BH), 256>>>(qkv);
    vsum_kernel<<<BH, 256>>>();

    cudaFuncSetAttribute(attn_kernel,
                         cudaFuncAttributeMaxDynamicSharedMemorySize, SMEM_DYN);
    attn_kernel<<<WORKERS, NTHREADS, SMEM_DYN>>>(seqlens, out_x, out_logits);
}

// round 10
// speedup vs baseline: 1.3964x; 1.1941x over previous
#include <cuda_runtime.h>
#include <cuda_bf16.h>
#include <cuda_fp16.h>
#include <math.h>
#include <stdint.h>

#define BB 2
#define SS 2048
#define HH 12
#define DD 64
#define BH (BB*HH)

#define TI 64
#define TJ 64
#define NTHREADS 128
#define NITILE (SS/TI)          // 32
#define NTASKS (BH*NITILE)      // 768
#define WORKERS 304

#define NELEM (BB*HH*SS*DD)
__device__ __nv_bfloat16 g_qh[NELEM], g_ql[NELEM];   // [bh][s][d]
__device__ __nv_bfloat16 g_kh[NELEM], g_kl[NELEM];   // [bh][s][d]
__device__ __half        g_vt[NELEM];                // [bh][d][s]
__device__ float         g_vsum[BH * DD];
__device__ int           g_task;

// smem tile layout: padded rows of 72 elems (144 B); 64 rows = 9216 B per array
#define ROWB 144
#define OKH 0
#define OKL 9216
#define OVH 18432
#define BUF_BYTES 27648
#define SMEM_DYN (2 * BUF_BYTES)

// ---------------------------------------------------------------------------
__device__ __forceinline__ void mma_bf16(float (&c)[4], const uint32_t* a,
                                         uint32_t b0, uint32_t b1) {
    asm volatile(
        "mma.sync.aligned.m16n8k16.row.col.f32.bf16.bf16.f32 "
        "{%0,%1,%2,%3}, {%4,%5,%6,%7}, {%8,%9}, {%0,%1,%2,%3};\n"
        : "+f"(c[0]), "+f"(c[1]), "+f"(c[2]), "+f"(c[3])
        : "r"(a[0]), "r"(a[1]), "r"(a[2]), "r"(a[3]), "r"(b0), "r"(b1));
}
__device__ __forceinline__ void mma_fp16(float (&c)[4], const uint32_t* a,
                                         uint32_t b0, uint32_t b1) {
    asm volatile(
        "mma.sync.aligned.m16n8k16.row.col.f32.f16.f16.f32 "
        "{%0,%1,%2,%3}, {%4,%5,%6,%7}, {%8,%9}, {%0,%1,%2,%3};\n"
        : "+f"(c[0]), "+f"(c[1]), "+f"(c[2]), "+f"(c[3])
        : "r"(a[0]), "r"(a[1]), "r"(a[2]), "r"(a[3]), "r"(b0), "r"(b1));
}

#define LDSM4(r0, r1, r2, r3, addr) \
    asm volatile("ldmatrix.sync.aligned.m8n8.x4.shared.b16 {%0,%1,%2,%3}, [%4];" \
        : "=r"(r0), "=r"(r1), "=r"(r2), "=r"(r3) : "r"(addr))

#define CP16(dst, src) \
    asm volatile("cp.async.cg.shared.global [%0], [%1], 16;" \
        :: "r"(dst), "l"(src) : "memory")
#define CP_COMMIT() asm volatile("cp.async.commit_group;" ::: "memory")
#define CP_WAIT(n)  asm volatile("cp.async.wait_group %0;" :: "n"(n) : "memory")

__device__ __forceinline__ uint32_t smem_u32(const void* p) {
    uint32_t a;
    asm("{ .reg .u64 t; cvta.to.shared.u64 t, %1; cvt.u32.u64 %0, t; }" : "=r"(a) : "l"(p));
    return a;
}
__device__ __forceinline__ uint32_t pack_half2(float lo, float hi) {
    __half2 t = __floats2half2_rn(lo, hi);
    return *(uint32_t*)&t;
}

// ---------------------------------------------------------------------------
__global__ void rotary_qk_kernel(const float* __restrict__ qkv,
                                 const float* __restrict__ cosb,
                                 const float* __restrict__ sinb) {
    int idx = blockIdx.x * blockDim.x + threadIdx.x;
    const int total = BB * SS * 2 * HH * 32;
    if (idx >= total) return;
    int d2 = idx & 31; int rest = idx >> 5;
    int h = rest % HH; rest /= HH;
    int t = rest & 1;  rest >>= 1;
    int s = rest % SS; int b = rest / SS;

    size_t qoff = ((((size_t)b * SS + s) * 3 + t) * HH + h) * DD + d2;
    float x1 = qkv[qoff];
    float x2 = qkv[qoff + 32];
    int coff = (s * 3 + t) * DD + d2;
    float c = cosb[coff], sn = sinb[coff];
    float o1 = x1 * c - x2 * sn;
    float o2 = x2 * c + x1 * sn;

    __nv_bfloat16 h1 = __float2bfloat16_rn(o1);
    __nv_bfloat16 l1 = __float2bfloat16_rn(o1 - __bfloat162float(h1));
    __nv_bfloat16 h2 = __float2bfloat16_rn(o2);
    __nv_bfloat16 l2 = __float2bfloat16_rn(o2 - __bfloat162float(h2));

    __nv_bfloat16* dh = (t == 0) ? g_qh : g_kh;
    __nv_bfloat16* dl = (t == 0) ? g_ql : g_kl;
    size_t doff = (((size_t)b * HH + h) * SS + s) * DD + d2;
    dh[doff] = h1; dh[doff + 32] = h2;
    dl[doff] = l1; dl[doff + 32] = l2;
}

// ---------------------------------------------------------------------------
__global__ void vtrans_kernel(const float* __restrict__ qkv) {
    __shared__ __half sT[64 * 72];
    const int bh = blockIdx.y;
    const int b = bh / HH, h = bh % HH;
    const int s0 = blockIdx.x * 64;
    const int tid = threadIdx.x;
    const int sl = tid >> 2;
    const int d2b = (tid & 3) * 8;
    const int s = s0 + sl;

    const float* base = qkv + (((size_t)(b * SS + s) * 3 + 2) * HH + h) * DD;
    #pragma unroll
    for (int i = 0; i < 8; i++) {
        int d = d2b + i;
        sT[d * 72 + sl]        = __float2half_rn(base[d]);
        sT[(d + 32) * 72 + sl] = __float2half_rn(base[d + 32]);
    }
    __syncthreads();
    #pragma unroll
    for (int c = tid; c < 512; c += 256) {
        int r = c >> 3, co = (c & 7) * 8;
        size_t dst = ((size_t)bh * DD + r) * SS + s0 + co;
        *(uint4*)(g_vt + dst) = *(const uint4*)(sT + r * 72 + co);
    }
}

// ---------------------------------------------------------------------------
// vsum + task-counter reset (stream-ordered before attn)
// ---------------------------------------------------------------------------
__global__ void vsum_kernel() {
    if (blockIdx.x == 0 && threadIdx.x == 0) g_task = 0;
    const int bh = blockIdx.x;
    const int tid = threadIdx.x;
    const int d = tid >> 2;
    const int q = tid & 3;
    const __half* src = g_vt + ((size_t)bh * DD + d) * SS + q * 512;
    float s = 0.f;
    #pragma unroll 8
    for (int i = 0; i < 64; i++) {
        uint4 v = *(const uint4*)(src + i * 8);
        const __half2* h2 = (const __half2*)&v;
        #pragma unroll
        for (int k = 0; k < 4; k++) {
            float2 f = __half22float2(h2[k]);
            s += f.x + f.y;
        }
    }
    s += __shfl_xor_sync(0xffffffffu, s, 1);
    s += __shfl_xor_sync(0xffffffffu, s, 2);
    if (q == 0) g_vsum[bh * DD + d] = s;
}

// ---------------------------------------------------------------------------
// persistent flash attention, 128 threads (4 warps), 2 CTAs/SM
// ---------------------------------------------------------------------------
__global__ void __launch_bounds__(NTHREADS, 2)
attn_kernel(const int* __restrict__ seqlens,
            float* __restrict__ out_x,
            float* __restrict__ out_logits) {
    extern __shared__ char smem[];
    const uint32_t sb = smem_u32(smem);
    __shared__ int sTask;

    const int tid = threadIdx.x;
    const int wid = tid >> 5;
    const int lane = tid & 31;
    const int lq = lane >> 2;
    const int lr = lane & 3;

    const int sl0 = seqlens[0];
    const int sl1 = seqlens[1];
    // LPT ordering: valid tasks of longer batch, valid of shorter, then masked
    const int bA = (sl0 >= sl1) ? 0 : 1;
    const int bBt = 1 - bA;
    const int slA = (bA == 0) ? sl0 : sl1;
    const int slB = (bA == 0) ? sl1 : sl0;
    const int ivA = (slA + TI - 1) / TI;        // valid i-tiles, <= 32
    const int ivB = (slB + TI - 1) / TI;
    const int nA = HH * ivA;
    const int nB = HH * ivB;
    const int mA = HH * (NITILE - ivA);

    const float inv2048 = 1.0f / 2048.0f;
    const uint32_t lmo = (uint32_t)(lane & 7) * ROWB + (uint32_t)((lane >> 3) & 3) * 16;

    for (;;) {
        if (tid == 0) sTask = atomicAdd(&g_task, 1);
        __syncthreads();
        const int t = sTask;
        if (t >= NTASKS) break;

        // ---- decode task -> (b, h, i-tile) ----
        int b, h, it;
        if (t < nA)            { b = bA;  h = t % HH;  it = t / HH; }
        else if (t < nA + nB)  { int u = t - nA; b = bBt; h = u % HH; it = u / HH; }
        else {
            int u = t - nA - nB;
            if (u < mA) { b = bA;  h = u % HH; it = ivA + u / HH; }
            else        { u -= mA; b = bBt; h = u % HH; it = ivB + u / HH; }
        }
        const int bh = b * HH + h;
        const int i0 = it * TI;
        const int seqlen = (b == 0) ? sl0 : sl1;

        // ---------- fully-masked i-tile: pure fill ----------
        if (i0 >= seqlen) {
            float4 fill = make_float4(-1e10f, -1e10f, -1e10f, -1e10f);
            float4* lg = (float4*)(out_logits + ((size_t)bh * SS + i0) * SS);
            #pragma unroll 8
            for (int c = tid; c < TI * SS / 4; c += NTHREADS)
                lg[c] = fill;
            const float* vs = g_vsum + bh * DD;
            float4* xo = (float4*)(out_x + ((size_t)bh * SS + i0) * DD);
            for (int c = tid; c < TI * DD / 4; c += NTHREADS) {
                int dcol = (c & 15) * 4;
                xo[c] = make_float4(vs[dcol] * inv2048, vs[dcol + 1] * inv2048,
                                    vs[dcol + 2] * inv2048, vs[dcol + 3] * inv2048);
            }
            continue;
        }

        const int jtmax = (seqlen + TJ - 1) / TJ;
        const size_t bh_off = (size_t)bh * SS * DD;
        const size_t v_off = (size_t)bh * DD * SS;

        // ---- persistent Q fragments (hi/lo) from gmem ----
        uint32_t aQh[16], aQl[16];
        {
            const __nv_bfloat16* q0 = g_qh + bh_off + (size_t)(i0 + wid * 16 + lq) * DD + 2 * lr;
            const __nv_bfloat16* q1 = g_ql + bh_off + (size_t)(i0 + wid * 16 + lq) * DD + 2 * lr;
            #pragma unroll
            for (int kt = 0; kt < 4; kt++) {
                aQh[kt*4+0] = *(const uint32_t*)(q0 + kt * 16);
                aQh[kt*4+1] = *(const uint32_t*)(q0 + 8 * DD + kt * 16);
                aQh[kt*4+2] = *(const uint32_t*)(q0 + kt * 16 + 8);
                aQh[kt*4+3] = *(const uint32_t*)(q0 + 8 * DD + kt * 16 + 8);
                aQl[kt*4+0] = *(const uint32_t*)(q1 + kt * 16);
                aQl[kt*4+1] = *(const uint32_t*)(q1 + 8 * DD + kt * 16);
                aQl[kt*4+2] = *(const uint32_t*)(q1 + kt * 16 + 8);
                aQl[kt*4+3] = *(const uint32_t*)(q1 + 8 * DD + kt * 16 + 8);
            }
        }

        const int rowA = i0 + wid * 16 + lq;
        const int rowB = rowA + 8;
        const bool rvA = rowA < seqlen;
        const bool rvB = rowB < seqlen;

        float mA_ = -INFINITY, mB_ = -INFINITY, lA = 0.f, lB = 0.f;
        float acc[8][4];
        #pragma unroll
        for (int n = 0; n < 8; n++)
            #pragma unroll
            for (int q = 0; q < 4; q++) acc[n][q] = 0.f;

        float* lgA = out_logits + ((size_t)bh * SS + rowA) * SS;
        float* lgB = out_logits + ((size_t)bh * SS + rowB) * SS;

        #define ISSUE_PREFETCH(JT, BUF) do { \
            uint32_t bba = sb + (BUF) * BUF_BYTES; \
            const __nv_bfloat16* _kh = g_kh + bh_off + (size_t)(JT) * TJ * DD; \
            const __nv_bfloat16* _kl = g_kl + bh_off + (size_t)(JT) * TJ * DD; \
            const __half* _v = g_vt + v_off + (size_t)(JT) * TJ; \
            _Pragma("unroll") \
            for (int c = tid; c < 512; c += NTHREADS) { \
                int r = c >> 3, co = (c & 7) * 8; \
                uint32_t dof = (uint32_t)r * ROWB + co * 2; \
                CP16(bba + OKH + dof, _kh + r * DD + co); \
                CP16(bba + OKL + dof, _kl + r * DD + co); \
                CP16(bba + OVH + dof, _v + (size_t)r * SS + co); \
            } \
            CP_COMMIT(); \
        } while (0)

        ISSUE_PREFETCH(0, 0);

        for (int jt = 0; jt < jtmax; jt++) {
            if (jt + 1 < jtmax) {
                ISSUE_PREFETCH(jt + 1, (jt + 1) & 1);
                CP_WAIT(1);
            } else {
                CP_WAIT(0);
            }
            __syncthreads();

            const uint32_t bba = sb + (jt & 1) * BUF_BYTES;
            const uint32_t uKh = bba + OKH, uKl = bba + OKL, uVh = bba + OVH;

            // ---- S = Q K^T (3-product bf16 split) ----
            float s[8][4];
            #pragma unroll
            for (int nt = 0; nt < 8; nt++) {
                #pragma unroll
                for (int q = 0; q < 4; q++) s[nt][q] = 0.f;
                uint32_t kb[8], lb[8];
                uint32_t a0 = uKh + nt * (8 * ROWB) + lmo;
                uint32_t a1 = uKl + nt * (8 * ROWB) + lmo;
                LDSM4(kb[0], kb[1], kb[2], kb[3], a0);
                LDSM4(kb[4], kb[5], kb[6], kb[7], a0 + 64);
                LDSM4(lb[0], lb[1], lb[2], lb[3], a1);
                LDSM4(lb[4], lb[5], lb[6], lb[7], a1 + 64);
                #pragma unroll
                for (int kt = 0; kt < 4; kt++) {
                    mma_bf16(s[nt], aQh + kt * 4, kb[2*kt], kb[2*kt+1]);
                    mma_bf16(s[nt], aQl + kt * 4, kb[2*kt], kb[2*kt+1]);
                    mma_bf16(s[nt], aQh + kt * 4, lb[2*kt], lb[2*kt+1]);
                }
            }

            // ---- scale + mask + stream logits ----
            const int jb = jt * TJ;
            #pragma unroll
            for (int nt = 0; nt < 8; nt++) {
                int col = jb + nt * 8 + 2 * lr;
                bool c0v = col < seqlen;
                bool c1v = (col + 1) < seqlen;
                float v0 = (rvA && c0v) ? s[nt][0] * 0.125f : -1e10f;
                float v1 = (rvA && c1v) ? s[nt][1] * 0.125f : -1e10f;
                float v2 = (rvB && c0v) ? s[nt][2] * 0.125f : -1e10f;
                float v3 = (rvB && c1v) ? s[nt][3] * 0.125f : -1e10f;
                *(float2*)(lgA + col) = make_float2(v0, v1);
                *(float2*)(lgB + col) = make_float2(v2, v3);
                s[nt][0] = v0; s[nt][1] = v1; s[nt][2] = v2; s[nt][3] = v3;
            }

            // ---- online softmax ----
            float tmA = -INFINITY, tmB = -INFINITY;
            #pragma unroll
            for (int nt = 0; nt < 8; nt++) {
                tmA = fmaxf(tmA, fmaxf(s[nt][0], s[nt][1]));
                tmB = fmaxf(tmB, fmaxf(s[nt][2], s[nt][3]));
            }
            tmA = fmaxf(tmA, __shfl_xor_sync(0xffffffffu, tmA, 1));
            tmA = fmaxf(tmA, __shfl_xor_sync(0xffffffffu, tmA, 2));
            tmB = fmaxf(tmB, __shfl_xor_sync(0xffffffffu, tmB, 1));
            tmB = fmaxf(tmB, __shfl_xor_sync(0xffffffffu, tmB, 2));

            float mnA = fmaxf(mA_, tmA), mnB = fmaxf(mB_, tmB);
            float fA = __expf(mA_ - mnA), fB = __expf(mB_ - mnB);
            mA_ = mnA; mB_ = mnB;

            float sumA = 0.f, sumB = 0.f;
            #pragma unroll
            for (int nt = 0; nt < 8; nt++) {
                s[nt][0] = __expf(s[nt][0] - mnA);
                s[nt][1] = __expf(s[nt][1] - mnA);
                s[nt][2] = __expf(s[nt][2] - mnB);
                s[nt][3] = __expf(s[nt][3] - mnB);
                sumA += s[nt][0] + s[nt][1];
                sumB += s[nt][2] + s[nt][3];
            }
            sumA += __shfl_xor_sync(0xffffffffu, sumA, 1);
            sumA += __shfl_xor_sync(0xffffffffu, sumA, 2);
            sumB += __shfl_xor_sync(0xffffffffu, sumB, 1);
            sumB += __shfl_xor_sync(0xffffffffu, sumB, 2);
            lA = lA * fA + sumA;
            lB = lB * fB + sumB;

            #pragma unroll
            for (int nt = 0; nt < 8; nt++) {
                acc[nt][0] *= fA; acc[nt][1] *= fA;
                acc[nt][2] *= fB; acc[nt][3] *= fB;
            }

            // ---- pack P into fp16 a-frags ----
            uint32_t aP[16];
            #pragma unroll
            for (int kt = 0; kt < 4; kt++) {
                #pragma unroll
                for (int g = 0; g < 4; g++) {
                    int nt = 2 * kt + (g >> 1);
                    float p0 = s[nt][(g & 1) ? 2 : 0];
                    float p1 = s[nt][(g & 1) ? 3 : 1];
                    aP[kt * 4 + g] = pack_half2(p0, p1);
                }
            }

            // ---- X += P V (single fp16 product) ----
            #pragma unroll
            for (int nt = 0; nt < 8; nt++) {
                uint32_t vb[8];
                uint32_t a0 = uVh + nt * (8 * ROWB) + lmo;
                LDSM4(vb[0], vb[1], vb[2], vb[3], a0);
                LDSM4(vb[4], vb[5], vb[6], vb[7], a0 + 64);
                #pragma unroll
                for (int kt = 0; kt < 4; kt++)
                    mma_fp16(acc[nt], aP + kt * 4, vb[2*kt], vb[2*kt+1]);
            }
            __syncthreads();
        }

        // ---- tail fill: logits cols [jtmax*TJ, SS) ----
        {
            const int ctail = SS - jtmax * TJ;
            if (ctail > 0) {
                float4 fill = make_float4(-1e10f, -1e10f, -1e10f, -1e10f);
                float* base = out_logits + ((size_t)bh * SS + i0) * SS + jtmax * TJ;
                const int c4 = ctail / 4;
                for (int c = tid; c < TI * c4; c += NTHREADS) {
                    int r = c / c4, cc = (c % c4) * 4;
                    *(float4*)(base + (size_t)r * SS + cc) = fill;
                }
            }
        }

        // ---- epilogue ----
        const float liA = 1.f / lA, liB = 1.f / lB;
        const float* vs = g_vsum + bh * DD;
        float* xA = out_x + ((size_t)bh * SS + rowA) * DD;
        float* xB = out_x + ((size_t)bh * SS + rowB) * DD;
        #pragma unroll
        for (int nt = 0; nt < 8; nt++) {
            int col = nt * 8 + 2 * lr;
            float a0, a1, b0, b1;
            if (rvA) { a0 = acc[nt][0] * liA; a1 = acc[nt][1] * liA; }
            else     { a0 = vs[col] * inv2048; a1 = vs[col + 1] * inv2048; }
            if (rvB) { b0 = acc[nt][2] * liB; b1 = acc[nt][3] * liB; }
            else     { b0 = vs[col] * inv2048; b1 = vs[col + 1] * inv2048; }
            *(float2*)(xA + col) = make_float2(a0, a1);
            *(float2*)(xB + col) = make_float2(b0, b1);
        }
    }
}

extern "C" void kernel_launch(void* const* d_in, const int* in_sizes, int n_in,
                              void* d_out, int out_size) {
    const float* qkv     = (const float*)d_in[0];
    const float* cosb    = (const float*)d_in[1];
    const float* sinb    = (const float*)d_in[2];
    const int*   seqlens = (const int*)d_in[3];

    float* out        = (float*)d_out;
    float* out_x      = out;                                 // [B,H,S,D]
    float* out_logits = out + (size_t)BB * HH * SS * DD;     // [B,H,S,S]

    const int total_qk = BB * SS * 2 * HH * 32;
    rotary_qk_kernel<<<(total_qk + 255) / 256, 256>>>(qkv, cosb, sinb);
    vtrans_kernel<<<dim3(SS / 64, BH), 256>>>(qkv);
    vsum_kernel<<<BH, 256>>>();

    cudaFuncSetAttribute(attn_kernel,
                         cudaFuncAttributeMaxDynamicSharedMemorySize, SMEM_DYN);
    attn_kernel<<<WORKERS, NTHREADS, SMEM_DYN>>>(seqlens, out_x, out_logits);
}